// round 12
// baseline (speedup 1.0000x reference)
#include <cuda_runtime.h>
#include <cuda_fp16.h>
#include <cstdint>

// ---------------------------------------------------------------------------
// GraphConvolutionLayer: out = segment_sum(vals[e] * (x@W)[src[e]] -> dst[e]) + bias
// R11 resubmit (infra ate the previous run):
//   - GEMM: cp.async 2-stage double buffer, BK=16 x 8 stages (29.2KB smem)
//   - gather: whole bucket in ONE coalesced 256B load (CAP=32=warp),
//     entries broadcast via shfl -> independent row LDGs
//   - fill: unchanged (measured-best, 4 edges/thread)
// ---------------------------------------------------------------------------

#define IN_F  128
#define OUT_F 64
#define MAX_NODES 100000
#define CAP 32
#define OVF_CAP 65536

__device__ __half g_support[(size_t)MAX_NODES * OUT_F];
__device__ int    g_count[MAX_NODES];
__device__ int2   g_bucket[(size_t)MAX_NODES * CAP];
__device__ int    g_ovf_count;
__device__ int4   g_ovf[OVF_CAP];

#define BM 128
#define BK 16
#define NSTAGE (IN_F / BK)    // 8
#define A_STRIDE 20   // 16 + 4 pad words (80B rows, 16B aligned; LDS conflict-free)
#define W_STRIDE 68   // 64 + 4 pad words

__device__ __forceinline__ uint32_t f2tf32(float v) {
    uint32_t t;
    asm("cvt.rna.tf32.f32 %0, %1;" : "=r"(t) : "f"(v));
    return t;
}

__device__ __forceinline__ void cp_async16(uint32_t dst, const void* src, int szbytes) {
    asm volatile("cp.async.ca.shared.global [%0], [%1], 16, %2;"
                 :: "r"(dst), "l"(src), "r"(szbytes));
}

// ---------------------------------------------------------------------------
// Kernel 1: cp.async-pipelined tf32 GEMM (+ zero counters)
// ---------------------------------------------------------------------------
__global__ __launch_bounds__(256)
void gemm_kernel(const float* __restrict__ A,   // [M,128]
                 const float* __restrict__ W,   // [128,64]
                 __half*      __restrict__ C,   // [M,64] fp16
                 int M) {
    {
        int t = blockIdx.x * blockDim.x + threadIdx.x;
        if (t < M) g_count[t] = 0;
        if (t == 0) g_ovf_count = 0;
    }

    __shared__ float As[2][BM * A_STRIDE];   // 2 x 10.0 KB
    __shared__ float Ws[2][BK * W_STRIDE];   // 2 x  4.3 KB

    int tid  = threadIdx.x;
    int lane = tid & 31;
    int wid  = tid >> 5;
    int wm   = wid >> 1;        // 0..3
    int wn   = wid & 1;         // 0..1
    int rowBase = blockIdx.x * BM;

    // A staging: 128 rows x 4 float4 = 512 copies, 2/thread
    int arow = tid >> 2, ac4 = tid & 3;      // arow 0..63, +64 for it=1
    // W staging: 16 rows x 16 float4 = 256 copies, 1/thread
    int wrow = tid >> 4, wn4 = tid & 15;

    auto issue = [&](int kOff, int b) {
        #pragma unroll
        for (int it = 0; it < 2; it++) {
            int row  = arow + it * 64;
            int grow = rowBase + row;
            uint32_t dst = (uint32_t)__cvta_generic_to_shared(
                &As[b][row * A_STRIDE + ac4 * 4]);
            cp_async16(dst, A + (size_t)grow * IN_F + kOff + ac4 * 4,
                       grow < M ? 16 : 0);               // zero-fill OOB rows
        }
        {
            uint32_t dst = (uint32_t)__cvta_generic_to_shared(
                &Ws[b][wrow * W_STRIDE + wn4 * 4]);
            cp_async16(dst, W + (size_t)(kOff + wrow) * OUT_F + wn4 * 4, 16);
        }
        asm volatile("cp.async.commit_group;");
    };

    float acc[2][4][4];
    #pragma unroll
    for (int i = 0; i < 2; i++)
        #pragma unroll
        for (int j = 0; j < 4; j++)
            #pragma unroll
            for (int q = 0; q < 4; q++) acc[i][j][q] = 0.f;

    int r = lane >> 2, c = lane & 3;

    issue(0, 0);   // prologue

    #pragma unroll
    for (int s = 0; s < NSTAGE; s++) {
        if (s < NSTAGE - 1) {
            issue((s + 1) * BK, (s + 1) & 1);
            asm volatile("cp.async.wait_group 1;");      // stage s resident
        } else {
            asm volatile("cp.async.wait_group 0;");
        }
        __syncthreads();

        const float* Ab = As[s & 1];
        const float* Wb = Ws[s & 1];

        #pragma unroll
        for (int kb = 0; kb < 2; kb++) {
            uint32_t fa[2][4];
            #pragma unroll
            for (int i = 0; i < 2; i++) {
                int m0 = (wm * 32 + i * 16 + r) * A_STRIDE + kb * 8 + c;
                fa[i][0] = f2tf32(Ab[m0]);
                fa[i][1] = f2tf32(Ab[m0 + 8 * A_STRIDE]);
                fa[i][2] = f2tf32(Ab[m0 + 4]);
                fa[i][3] = f2tf32(Ab[m0 + 8 * A_STRIDE + 4]);
            }
            uint32_t fb[4][2];
            #pragma unroll
            for (int j = 0; j < 4; j++) {
                int b0 = (kb * 8 + c) * W_STRIDE + wn * 32 + j * 8 + r;
                fb[j][0] = f2tf32(Wb[b0]);
                fb[j][1] = f2tf32(Wb[b0 + 4 * W_STRIDE]);
            }
            #pragma unroll
            for (int i = 0; i < 2; i++)
                #pragma unroll
                for (int j = 0; j < 4; j++) {
                    asm volatile(
                        "mma.sync.aligned.m16n8k8.row.col.f32.tf32.tf32.f32 "
                        "{%0,%1,%2,%3}, {%4,%5,%6,%7}, {%8,%9}, {%0,%1,%2,%3};"
                        : "+f"(acc[i][j][0]), "+f"(acc[i][j][1]),
                          "+f"(acc[i][j][2]), "+f"(acc[i][j][3])
                        : "r"(fa[i][0]), "r"(fa[i][1]), "r"(fa[i][2]), "r"(fa[i][3]),
                          "r"(fb[j][0]), "r"(fb[j][1]));
                }
        }
        __syncthreads();   // reads of buf[s&1] complete before re-issue
    }

    // epilogue: fp16 store (validated layout)
    #pragma unroll
    for (int i = 0; i < 2; i++) {
        int r0 = rowBase + wm * 32 + i * 16 + r;
        int r1 = r0 + 8;
        #pragma unroll
        for (int j = 0; j < 4; j++) {
            int cbase = wn * 32 + j * 8 + c * 2;
            if (r0 < M) {
                __half2 h = __float22half2_rn(make_float2(acc[i][j][0], acc[i][j][1]));
                *reinterpret_cast<uint32_t*>(C + (size_t)r0 * OUT_F + cbase) = *(uint32_t*)&h;
            }
            if (r1 < M) {
                __half2 h = __float22half2_rn(make_float2(acc[i][j][2], acc[i][j][3]));
                *reinterpret_cast<uint32_t*>(C + (size_t)r1 * OUT_F + cbase) = *(uint32_t*)&h;
            }
        }
    }
}

// ---------------------------------------------------------------------------
// Kernel 2: fill — 4 edges per thread (unchanged, measured-best)
// ---------------------------------------------------------------------------
__global__ __launch_bounds__(256)
void fill_kernel(const int*   __restrict__ src,
                 const int*   __restrict__ dst,
                 const float* __restrict__ vals,
                 int nE) {
    int t  = blockIdx.x * blockDim.x + threadIdx.x;
    int e0 = t * 4;
    if (e0 >= nE) return;

    if (e0 + 4 <= nE) {
        int4   s4 = *reinterpret_cast<const int4*>(src + e0);
        int4   d4 = *reinterpret_cast<const int4*>(dst + e0);
        float4 v4 = *reinterpret_cast<const float4*>(vals + e0);
        int ss[4] = {s4.x, s4.y, s4.z, s4.w};
        int dd[4] = {d4.x, d4.y, d4.z, d4.w};
        float vv[4] = {v4.x, v4.y, v4.z, v4.w};
        int pos[4];
        #pragma unroll
        for (int i = 0; i < 4; i++)
            pos[i] = atomicAdd(&g_count[dd[i]], 1);
        #pragma unroll
        for (int i = 0; i < 4; i++) {
            if (pos[i] < CAP) {
                g_bucket[(size_t)dd[i] * CAP + pos[i]] = make_int2(ss[i], __float_as_int(vv[i]));
            } else {
                int o = atomicAdd(&g_ovf_count, 1);
                if (o < OVF_CAP) g_ovf[o] = make_int4(ss[i], dd[i], __float_as_int(vv[i]), 0);
            }
        }
    } else {
        for (int e = e0; e < nE; e++) {
            int   s = __ldg(&src[e]);
            int   d = __ldg(&dst[e]);
            float v = __ldg(&vals[e]);
            int pos = atomicAdd(&g_count[d], 1);
            if (pos < CAP) {
                g_bucket[(size_t)d * CAP + pos] = make_int2(s, __float_as_int(v));
            } else {
                int o = atomicAdd(&g_ovf_count, 1);
                if (o < OVF_CAP) g_ovf[o] = make_int4(s, d, __float_as_int(v), 0);
            }
        }
    }
}

// ---------------------------------------------------------------------------
// Kernel 3: gather — one warp per dst node; bucket loaded coalesced (lane i
// holds entry i), entries broadcast via shfl -> independent row loads
// ---------------------------------------------------------------------------
__global__ __launch_bounds__(256)
void gather_kernel(const __half* __restrict__ support,
                   const float*  __restrict__ bias,
                   float* __restrict__ out, int M) {
    int w    = (blockIdx.x * blockDim.x + threadIdx.x) >> 5;
    int lane = threadIdx.x & 31;
    if (w >= M) return;

    int deg = g_count[w];
    int nb  = deg < CAP ? deg : CAP;

    // one coalesced 256B load fetches the whole bucket (CAP == warp size)
    int2 myent = g_bucket[(size_t)w * CAP + lane];

    float2 acc = make_float2(0.f, 0.f);

    #pragma unroll 4
    for (int j = 0; j < nb; j++) {
        int   s = __shfl_sync(0xFFFFFFFFu, myent.x, j);
        float v = __int_as_float(__shfl_sync(0xFFFFFFFFu, myent.y, j));
        uint32_t h2 = __ldg(reinterpret_cast<const uint32_t*>(
            support + (size_t)s * OUT_F) + lane);
        float2 f = __half22float2(*reinterpret_cast<__half2*>(&h2));
        acc.x += v * f.x;
        acc.y += v * f.y;
    }

    // overflow backstop (only nodes that exceeded CAP; list is ~tens)
    if (deg > CAP) {
        int n = g_ovf_count;
        if (n > OVF_CAP) n = OVF_CAP;
        for (int i = 0; i < n; i++) {
            int4 r = g_ovf[i];
            if (r.y == w) {
                float v = __int_as_float(r.z);
                uint32_t h2 = __ldg(reinterpret_cast<const uint32_t*>(
                    support + (size_t)r.x * OUT_F) + lane);
                float2 f = __half22float2(*reinterpret_cast<__half2*>(&h2));
                acc.x += v * f.x;
                acc.y += v * f.y;
            }
        }
    }

    float2 b = __ldg(reinterpret_cast<const float2*>(bias) + lane);
    float2 rr = make_float2(acc.x + b.x, acc.y + b.y);
    *reinterpret_cast<float2*>(out + (size_t)w * OUT_F + 2 * lane) = rr;
}

// ---------------------------------------------------------------------------
extern "C" void kernel_launch(void* const* d_in, const int* in_sizes, int n_in,
                              void* d_out, int out_size) {
    const float* x        = (const float*)d_in[0];
    const float* weight   = (const float*)d_in[1];
    const float* bias     = (const float*)d_in[2];
    const int*   edge_src = (const int*)  d_in[3];
    const int*   edge_dst = (const int*)  d_in[4];
    const float* edge_val = (const float*)d_in[5];
    float* out = (float*)d_out;

    int M  = in_sizes[0] / IN_F;
    int nE = in_sizes[3];

    __half* support; cudaGetSymbolAddress((void**)&support, g_support);

    gemm_kernel<<<(M + BM - 1) / BM, 256>>>(x, weight, support, M);

    {
        int threadsNeeded = (nE + 3) / 4;
        fill_kernel<<<(threadsNeeded + 255) / 256, 256>>>(edge_src, edge_dst, edge_val, nE);
    }

    gather_kernel<<<(M * 32 + 255) / 256, 256>>>(support, bias, out, M);
}

// round 14
// speedup vs baseline: 1.0492x; 1.0492x over previous
#include <cuda_runtime.h>
#include <cuda_fp16.h>
#include <cstdint>

// ---------------------------------------------------------------------------
// GraphConvolutionLayer: out = segment_sum(vals[e] * (x@W)[src[e]] -> dst[e]) + bias
// R13 resubmit (infra ate the previous run):
//   GEMM on fp16 mma.m16n8k16 (half the mma instruction count vs tf32 k8;
//   fp16 mantissa == tf32 mantissa so precision unchanged).
//   fill/gather = R9 measured-best shapes.
// ---------------------------------------------------------------------------

#define IN_F  128
#define OUT_F 64
#define MAX_NODES 100000
#define CAP 32
#define OVF_CAP 65536

__device__ __half g_support[(size_t)MAX_NODES * OUT_F];
__device__ int    g_count[MAX_NODES];
__device__ int2   g_bucket[(size_t)MAX_NODES * CAP];
__device__ int    g_ovf_count;
__device__ int4   g_ovf[OVF_CAP];

#define BM 128
#define BK 32                 // k per stage
#define NSTAGE (IN_F / BK)    // 4
#define A_STRIDE 20           // words per A smem row (16 data + 4 pad)
#define B_STRIDE 20           // words per B smem row (16 data + 4 pad)

// ---------------------------------------------------------------------------
// Kernel 1: fp16 HMMA GEMM, register-prefetch pipeline (+ zero counters)
// ---------------------------------------------------------------------------
__global__ __launch_bounds__(256)
void gemm_kernel(const float* __restrict__ A,   // [M,128]
                 const float* __restrict__ W,   // [128,64]
                 __half*      __restrict__ C,   // [M,64] fp16
                 int M) {
    {
        int t = blockIdx.x * blockDim.x + threadIdx.x;
        if (t < M) g_count[t] = 0;
        if (t == 0) g_ovf_count = 0;
    }

    __shared__ uint32_t As[BM * A_STRIDE];      // 10 KB (fp16 pairs)
    __shared__ uint32_t Bs[OUT_F * B_STRIDE];   //  5 KB (W transposed [n][k])

    int tid  = threadIdx.x;
    int lane = tid & 31;
    int wid  = tid >> 5;
    int wm   = wid >> 1;        // 0..3 (M groups of 32)
    int wn   = wid & 1;         // 0..1 (N groups of 32)
    int rowBase = blockIdx.x * BM;

    // A staging: 128 rows x 8 float4 = 1024 tasks, 4/thread
    int arow = tid >> 3, aq = tid & 7;          // +32-row steps per it
    // W staging (transpose): thread owns n = tid>>2, k-octet = (tid&3)*8
    int wn_t = tid >> 2, wk8 = (tid & 3) * 8;

    float4 pa[4];
    float  pw[8];

    auto prefetch = [&](int kOff) {
        #pragma unroll
        for (int it = 0; it < 4; it++) {
            int grow = rowBase + arow + it * 32;
            pa[it] = (grow < M)
                ? *reinterpret_cast<const float4*>(A + (size_t)grow * IN_F + kOff + aq * 4)
                : make_float4(0.f, 0.f, 0.f, 0.f);
        }
        #pragma unroll
        for (int i = 0; i < 8; i++)
            pw[i] = W[(size_t)(kOff + wk8 + i) * OUT_F + wn_t];
    };

    auto stage = [&]() {
        #pragma unroll
        for (int it = 0; it < 4; it++) {
            __half2 h01 = __floats2half2_rn(pa[it].x, pa[it].y);
            __half2 h23 = __floats2half2_rn(pa[it].z, pa[it].w);
            uint2 u = make_uint2(*(uint32_t*)&h01, *(uint32_t*)&h23);
            *reinterpret_cast<uint2*>(&As[(arow + it * 32) * A_STRIDE + aq * 2]) = u;
        }
        {
            uint4 u;
            __half2 h0 = __floats2half2_rn(pw[0], pw[1]);
            __half2 h1 = __floats2half2_rn(pw[2], pw[3]);
            __half2 h2 = __floats2half2_rn(pw[4], pw[5]);
            __half2 h3 = __floats2half2_rn(pw[6], pw[7]);
            u.x = *(uint32_t*)&h0; u.y = *(uint32_t*)&h1;
            u.z = *(uint32_t*)&h2; u.w = *(uint32_t*)&h3;
            *reinterpret_cast<uint4*>(&Bs[wn_t * B_STRIDE + (wk8 >> 1)]) = u;
        }
    };

    float acc[2][4][4];
    #pragma unroll
    for (int i = 0; i < 2; i++)
        #pragma unroll
        for (int j = 0; j < 4; j++)
            #pragma unroll
            for (int q = 0; q < 4; q++) acc[i][j][q] = 0.f;

    int r = lane >> 2, c = lane & 3;

    prefetch(0);

    #pragma unroll
    for (int s = 0; s < NSTAGE; s++) {
        stage();
        __syncthreads();
        if (s < NSTAGE - 1) prefetch((s + 1) * BK);

        #pragma unroll
        for (int ks = 0; ks < 2; ks++) {           // two k16 steps per stage
            uint32_t fa[2][4];
            #pragma unroll
            for (int i = 0; i < 2; i++) {
                int m0 = (wm * 32 + i * 16 + r) * A_STRIDE + ks * 8 + c;
                fa[i][0] = As[m0];                  // (r,   2c..2c+1)
                fa[i][1] = As[m0 + 8 * A_STRIDE];   // (r+8, 2c..2c+1)
                fa[i][2] = As[m0 + 4];              // (r,   2c+8..)
                fa[i][3] = As[m0 + 8 * A_STRIDE + 4];
            }
            uint32_t fb[4][2];
            #pragma unroll
            for (int j = 0; j < 4; j++) {
                int b0 = (wn * 32 + j * 8 + r) * B_STRIDE + ks * 8 + c;
                fb[j][0] = Bs[b0];                  // (n=r grp, k=2c..2c+1)
                fb[j][1] = Bs[b0 + 4];              // (n,       k=2c+8..)
            }
            #pragma unroll
            for (int i = 0; i < 2; i++)
                #pragma unroll
                for (int j = 0; j < 4; j++) {
                    asm volatile(
                        "mma.sync.aligned.m16n8k16.row.col.f32.f16.f16.f32 "
                        "{%0,%1,%2,%3}, {%4,%5,%6,%7}, {%8,%9}, {%0,%1,%2,%3};"
                        : "+f"(acc[i][j][0]), "+f"(acc[i][j][1]),
                          "+f"(acc[i][j][2]), "+f"(acc[i][j][3])
                        : "r"(fa[i][0]), "r"(fa[i][1]), "r"(fa[i][2]), "r"(fa[i][3]),
                          "r"(fb[j][0]), "r"(fb[j][1]));
                }
        }
        __syncthreads();
    }

    // epilogue: fp16 store (same validated D layout as m16n8k8)
    #pragma unroll
    for (int i = 0; i < 2; i++) {
        int r0 = rowBase + wm * 32 + i * 16 + r;
        int r1 = r0 + 8;
        #pragma unroll
        for (int j = 0; j < 4; j++) {
            int cbase = wn * 32 + j * 8 + c * 2;
            if (r0 < M) {
                __half2 h = __float22half2_rn(make_float2(acc[i][j][0], acc[i][j][1]));
                *reinterpret_cast<uint32_t*>(C + (size_t)r0 * OUT_F + cbase) = *(uint32_t*)&h;
            }
            if (r1 < M) {
                __half2 h = __float22half2_rn(make_float2(acc[i][j][2], acc[i][j][3]));
                *reinterpret_cast<uint32_t*>(C + (size_t)r1 * OUT_F + cbase) = *(uint32_t*)&h;
            }
        }
    }
}

// ---------------------------------------------------------------------------
// Kernel 2: fill — 4 edges per thread (measured-best)
// ---------------------------------------------------------------------------
__global__ __launch_bounds__(256)
void fill_kernel(const int*   __restrict__ src,
                 const int*   __restrict__ dst,
                 const float* __restrict__ vals,
                 int nE) {
    int t  = blockIdx.x * blockDim.x + threadIdx.x;
    int e0 = t * 4;
    if (e0 >= nE) return;

    if (e0 + 4 <= nE) {
        int4   s4 = *reinterpret_cast<const int4*>(src + e0);
        int4   d4 = *reinterpret_cast<const int4*>(dst + e0);
        float4 v4 = *reinterpret_cast<const float4*>(vals + e0);
        int ss[4] = {s4.x, s4.y, s4.z, s4.w};
        int dd[4] = {d4.x, d4.y, d4.z, d4.w};
        float vv[4] = {v4.x, v4.y, v4.z, v4.w};
        int pos[4];
        #pragma unroll
        for (int i = 0; i < 4; i++)
            pos[i] = atomicAdd(&g_count[dd[i]], 1);
        #pragma unroll
        for (int i = 0; i < 4; i++) {
            if (pos[i] < CAP) {
                g_bucket[(size_t)dd[i] * CAP + pos[i]] = make_int2(ss[i], __float_as_int(vv[i]));
            } else {
                int o = atomicAdd(&g_ovf_count, 1);
                if (o < OVF_CAP) g_ovf[o] = make_int4(ss[i], dd[i], __float_as_int(vv[i]), 0);
            }
        }
    } else {
        for (int e = e0; e < nE; e++) {
            int   s = __ldg(&src[e]);
            int   d = __ldg(&dst[e]);
            float v = __ldg(&vals[e]);
            int pos = atomicAdd(&g_count[d], 1);
            if (pos < CAP) {
                g_bucket[(size_t)d * CAP + pos] = make_int2(s, __float_as_int(v));
            } else {
                int o = atomicAdd(&g_ovf_count, 1);
                if (o < OVF_CAP) g_ovf[o] = make_int4(s, d, __float_as_int(v), 0);
            }
        }
    }
}

// ---------------------------------------------------------------------------
// Kernel 3: gather — one warp per dst node (R9 measured-best shape)
// ---------------------------------------------------------------------------
__global__ __launch_bounds__(256)
void gather_kernel(const __half* __restrict__ support,
                   const float*  __restrict__ bias,
                   float* __restrict__ out, int M) {
    int w    = (blockIdx.x * blockDim.x + threadIdx.x) >> 5;
    int lane = threadIdx.x & 31;
    if (w >= M) return;

    int deg = g_count[w];
    int nb  = deg < CAP ? deg : CAP;

    float2 acc = make_float2(0.f, 0.f);
    const int2* bkt = g_bucket + (size_t)w * CAP;

    #pragma unroll 4
    for (int j = 0; j < nb; j++) {
        int2 pr = __ldg(&bkt[j]);                          // warp-broadcast
        float v = __int_as_float(pr.y);
        const uint32_t* row = reinterpret_cast<const uint32_t*>(
            support + (size_t)pr.x * OUT_F);
        uint32_t h2raw = __ldg(&row[lane]);
        float2 f = __half22float2(*reinterpret_cast<__half2*>(&h2raw));
        acc.x += v * f.x;
        acc.y += v * f.y;
    }

    if (deg > CAP) {
        int n = g_ovf_count;
        if (n > OVF_CAP) n = OVF_CAP;
        for (int i = 0; i < n; i++) {
            int4 r = g_ovf[i];
            if (r.y == w) {
                float v = __int_as_float(r.z);
                const uint32_t* row = reinterpret_cast<const uint32_t*>(
                    support + (size_t)r.x * OUT_F);
                uint32_t h2raw = __ldg(&row[lane]);
                float2 f = __half22float2(*reinterpret_cast<__half2*>(&h2raw));
                acc.x += v * f.x;
                acc.y += v * f.y;
            }
        }
    }

    float2 b = __ldg(reinterpret_cast<const float2*>(bias) + lane);
    float2 rr = make_float2(acc.x + b.x, acc.y + b.y);
    *reinterpret_cast<float2*>(out + (size_t)w * OUT_F + 2 * lane) = rr;
}

// ---------------------------------------------------------------------------
extern "C" void kernel_launch(void* const* d_in, const int* in_sizes, int n_in,
                              void* d_out, int out_size) {
    const float* x        = (const float*)d_in[0];
    const float* weight   = (const float*)d_in[1];
    const float* bias     = (const float*)d_in[2];
    const int*   edge_src = (const int*)  d_in[3];
    const int*   edge_dst = (const int*)  d_in[4];
    const float* edge_val = (const float*)d_in[5];
    float* out = (float*)d_out;

    int M  = in_sizes[0] / IN_F;
    int nE = in_sizes[3];

    __half* support; cudaGetSymbolAddress((void**)&support, g_support);

    gemm_kernel<<<(M + BM - 1) / BM, 256>>>(x, weight, support, M);

    {
        int threadsNeeded = (nE + 3) / 4;
        fill_kernel<<<(threadsNeeded + 255) / 256, 256>>>(edge_src, edge_dst, edge_val, nE);
    }

    gather_kernel<<<(M * 32 + 255) / 256, 256>>>(support, bias, out, M);
}

// round 17
// speedup vs baseline: 1.0984x; 1.0469x over previous
#include <cuda_runtime.h>
#include <cuda_fp16.h>
#include <cstdint>

// ---------------------------------------------------------------------------
// GraphConvolutionLayer: out = segment_sum(vals[e] * (x@W)[src[e]] -> dst[e]) + bias
// R15 source, third attempt (infra ate two runs):
//   GEMM (fp16 HMMA, 22.8us) and fill (4 edges/thread, ~24us) fused into ONE
//   grid with 1:2 block-type interleave so every wave overlaps DRAM-bound
//   GEMM with latency-bound fill. gather = R9 measured-best shape.
// ---------------------------------------------------------------------------

#define IN_F  128
#define OUT_F 64
#define MAX_NODES 100000
#define CAP 32
#define OVF_CAP 65536

__device__ __half g_support[(size_t)MAX_NODES * OUT_F];
__device__ int    g_count[MAX_NODES];
__device__ int2   g_bucket[(size_t)MAX_NODES * CAP];
__device__ int    g_ovf_count;
__device__ int4   g_ovf[OVF_CAP];

#define BM 128
#define BK 32                 // k per stage
#define NSTAGE (IN_F / BK)    // 4
#define A_STRIDE 20           // words per A smem row (16 data + 4 pad)
#define B_STRIDE 20           // words per B smem row (16 data + 4 pad)

// ---------------------------------------------------------------------------
// Kernel 1 (fused): b%3==0 -> GEMM tile b/3 ; otherwise -> fill chunk
// ---------------------------------------------------------------------------
__global__ __launch_bounds__(256)
void gemm_fill_kernel(const float* __restrict__ A,   // [M,128]
                      const float* __restrict__ W,   // [128,64]
                      __half*      __restrict__ C,   // [M,64] fp16
                      int M, int nGemm,
                      const int*   __restrict__ esrc,
                      const int*   __restrict__ edst,
                      const float* __restrict__ evals,
                      int nE) {
    int b = blockIdx.x;
    bool isGemm = ((b % 3) == 0) && (b / 3 < nGemm);

    if (!isGemm) {
        // ---------------- fill: 4 edges per thread ----------------
        int gemmBefore = min(b / 3 + 1, nGemm);
        int fb = b - gemmBefore;                 // fill block index (contiguous)
        int t  = fb * blockDim.x + threadIdx.x;
        int e0 = t * 4;
        if (e0 >= nE) return;

        if (e0 + 4 <= nE) {
            int4   s4 = *reinterpret_cast<const int4*>(esrc + e0);
            int4   d4 = *reinterpret_cast<const int4*>(edst + e0);
            float4 v4 = *reinterpret_cast<const float4*>(evals + e0);
            int ss[4] = {s4.x, s4.y, s4.z, s4.w};
            int dd[4] = {d4.x, d4.y, d4.z, d4.w};
            float vv[4] = {v4.x, v4.y, v4.z, v4.w};
            int pos[4];
            #pragma unroll
            for (int i = 0; i < 4; i++)
                pos[i] = atomicAdd(&g_count[dd[i]], 1);
            #pragma unroll
            for (int i = 0; i < 4; i++) {
                if (pos[i] < CAP) {
                    g_bucket[(size_t)dd[i] * CAP + pos[i]] =
                        make_int2(ss[i], __float_as_int(vv[i]));
                } else {
                    int o = atomicAdd(&g_ovf_count, 1);
                    if (o < OVF_CAP)
                        g_ovf[o] = make_int4(ss[i], dd[i], __float_as_int(vv[i]), 0);
                }
            }
        } else {
            for (int e = e0; e < nE; e++) {
                int   s = __ldg(&esrc[e]);
                int   d = __ldg(&edst[e]);
                float v = __ldg(&evals[e]);
                int pos = atomicAdd(&g_count[d], 1);
                if (pos < CAP) {
                    g_bucket[(size_t)d * CAP + pos] = make_int2(s, __float_as_int(v));
                } else {
                    int o = atomicAdd(&g_ovf_count, 1);
                    if (o < OVF_CAP) g_ovf[o] = make_int4(s, d, __float_as_int(v), 0);
                }
            }
        }
        return;
    }

    // ---------------- GEMM tile ----------------
    __shared__ uint32_t As[BM * A_STRIDE];      // 10 KB (fp16 pairs)
    __shared__ uint32_t Bs[OUT_F * B_STRIDE];   //  5 KB (W transposed [n][k])

    int tid  = threadIdx.x;
    int lane = tid & 31;
    int wid  = tid >> 5;
    int wm   = wid >> 1;
    int wn   = wid & 1;
    int rowBase = (b / 3) * BM;

    int arow = tid >> 3, aq = tid & 7;
    int wn_t = tid >> 2, wk8 = (tid & 3) * 8;

    float4 pa[4];
    float  pw[8];

    auto prefetch = [&](int kOff) {
        #pragma unroll
        for (int it = 0; it < 4; it++) {
            int grow = rowBase + arow + it * 32;
            pa[it] = (grow < M)
                ? *reinterpret_cast<const float4*>(A + (size_t)grow * IN_F + kOff + aq * 4)
                : make_float4(0.f, 0.f, 0.f, 0.f);
        }
        #pragma unroll
        for (int i = 0; i < 8; i++)
            pw[i] = W[(size_t)(kOff + wk8 + i) * OUT_F + wn_t];
    };

    auto stage = [&]() {
        #pragma unroll
        for (int it = 0; it < 4; it++) {
            __half2 h01 = __floats2half2_rn(pa[it].x, pa[it].y);
            __half2 h23 = __floats2half2_rn(pa[it].z, pa[it].w);
            uint2 u = make_uint2(*(uint32_t*)&h01, *(uint32_t*)&h23);
            *reinterpret_cast<uint2*>(&As[(arow + it * 32) * A_STRIDE + aq * 2]) = u;
        }
        {
            uint4 u;
            __half2 h0 = __floats2half2_rn(pw[0], pw[1]);
            __half2 h1 = __floats2half2_rn(pw[2], pw[3]);
            __half2 h2 = __floats2half2_rn(pw[4], pw[5]);
            __half2 h3 = __floats2half2_rn(pw[6], pw[7]);
            u.x = *(uint32_t*)&h0; u.y = *(uint32_t*)&h1;
            u.z = *(uint32_t*)&h2; u.w = *(uint32_t*)&h3;
            *reinterpret_cast<uint4*>(&Bs[wn_t * B_STRIDE + (wk8 >> 1)]) = u;
        }
    };

    float acc[2][4][4];
    #pragma unroll
    for (int i = 0; i < 2; i++)
        #pragma unroll
        for (int j = 0; j < 4; j++)
            #pragma unroll
            for (int q = 0; q < 4; q++) acc[i][j][q] = 0.f;

    int r = lane >> 2, c = lane & 3;

    prefetch(0);

    #pragma unroll
    for (int s = 0; s < NSTAGE; s++) {
        stage();
        __syncthreads();
        if (s < NSTAGE - 1) prefetch((s + 1) * BK);

        #pragma unroll
        for (int ks = 0; ks < 2; ks++) {
            uint32_t fa[2][4];
            #pragma unroll
            for (int i = 0; i < 2; i++) {
                int m0 = (wm * 32 + i * 16 + r) * A_STRIDE + ks * 8 + c;
                fa[i][0] = As[m0];
                fa[i][1] = As[m0 + 8 * A_STRIDE];
                fa[i][2] = As[m0 + 4];
                fa[i][3] = As[m0 + 8 * A_STRIDE + 4];
            }
            uint32_t fb[4][2];
            #pragma unroll
            for (int j = 0; j < 4; j++) {
                int b0 = (wn * 32 + j * 8 + r) * B_STRIDE + ks * 8 + c;
                fb[j][0] = Bs[b0];
                fb[j][1] = Bs[b0 + 4];
            }
            #pragma unroll
            for (int i = 0; i < 2; i++)
                #pragma unroll
                for (int j = 0; j < 4; j++) {
                    asm volatile(
                        "mma.sync.aligned.m16n8k16.row.col.f32.f16.f16.f32 "
                        "{%0,%1,%2,%3}, {%4,%5,%6,%7}, {%8,%9}, {%0,%1,%2,%3};"
                        : "+f"(acc[i][j][0]), "+f"(acc[i][j][1]),
                          "+f"(acc[i][j][2]), "+f"(acc[i][j][3])
                        : "r"(fa[i][0]), "r"(fa[i][1]), "r"(fa[i][2]), "r"(fa[i][3]),
                          "r"(fb[j][0]), "r"(fb[j][1]));
                }
        }
        __syncthreads();
    }

    #pragma unroll
    for (int i = 0; i < 2; i++) {
        int r0 = rowBase + wm * 32 + i * 16 + r;
        int r1 = r0 + 8;
        #pragma unroll
        for (int j = 0; j < 4; j++) {
            int cbase = wn * 32 + j * 8 + c * 2;
            if (r0 < M) {
                __half2 h = __float22half2_rn(make_float2(acc[i][j][0], acc[i][j][1]));
                *reinterpret_cast<uint32_t*>(C + (size_t)r0 * OUT_F + cbase) = *(uint32_t*)&h;
            }
            if (r1 < M) {
                __half2 h = __float22half2_rn(make_float2(acc[i][j][2], acc[i][j][3]));
                *reinterpret_cast<uint32_t*>(C + (size_t)r1 * OUT_F + cbase) = *(uint32_t*)&h;
            }
        }
    }
}

// ---------------------------------------------------------------------------
// Kernel 2: gather — one warp per dst node (R9 measured-best shape)
// ---------------------------------------------------------------------------
__global__ __launch_bounds__(256)
void gather_kernel(const __half* __restrict__ support,
                   const float*  __restrict__ bias,
                   float* __restrict__ out, int M) {
    int w    = (blockIdx.x * blockDim.x + threadIdx.x) >> 5;
    int lane = threadIdx.x & 31;
    if (w >= M) return;

    int deg = g_count[w];
    int nb  = deg < CAP ? deg : CAP;

    float2 acc = make_float2(0.f, 0.f);
    const int2* bkt = g_bucket + (size_t)w * CAP;

    #pragma unroll 4
    for (int j = 0; j < nb; j++) {
        int2 pr = __ldg(&bkt[j]);                          // warp-broadcast
        float v = __int_as_float(pr.y);
        const uint32_t* row = reinterpret_cast<const uint32_t*>(
            support + (size_t)pr.x * OUT_F);
        uint32_t h2raw = __ldg(&row[lane]);
        float2 f = __half22float2(*reinterpret_cast<__half2*>(&h2raw));
        acc.x += v * f.x;
        acc.y += v * f.y;
    }

    if (deg > CAP) {
        int n = g_ovf_count;
        if (n > OVF_CAP) n = OVF_CAP;
        for (int i = 0; i < n; i++) {
            int4 r = g_ovf[i];
            if (r.y == w) {
                float v = __int_as_float(r.z);
                const uint32_t* row = reinterpret_cast<const uint32_t*>(
                    support + (size_t)r.x * OUT_F);
                uint32_t h2raw = __ldg(&row[lane]);
                float2 f = __half22float2(*reinterpret_cast<__half2*>(&h2raw));
                acc.x += v * f.x;
                acc.y += v * f.y;
            }
        }
    }

    float2 b = __ldg(reinterpret_cast<const float2*>(bias) + lane);
    float2 rr = make_float2(acc.x + b.x, acc.y + b.y);
    *reinterpret_cast<float2*>(out + (size_t)w * OUT_F + 2 * lane) = rr;
}

// ---------------------------------------------------------------------------
extern "C" void kernel_launch(void* const* d_in, const int* in_sizes, int n_in,
                              void* d_out, int out_size) {
    const float* x        = (const float*)d_in[0];
    const float* weight   = (const float*)d_in[1];
    const float* bias     = (const float*)d_in[2];
    const int*   edge_src = (const int*)  d_in[3];
    const int*   edge_dst = (const int*)  d_in[4];
    const float* edge_val = (const float*)d_in[5];
    float* out = (float*)d_out;

    int M  = in_sizes[0] / IN_F;
    int nE = in_sizes[3];

    __half* support; cudaGetSymbolAddress((void**)&support, g_support);
    int*    countp;  cudaGetSymbolAddress((void**)&countp, g_count);
    int*    ovfcp;   cudaGetSymbolAddress((void**)&ovfcp, g_ovf_count);

    // zero bucket counters (kernel-boundary ordered before fused kernel)
    cudaMemsetAsync(countp, 0, (size_t)M * sizeof(int));
    cudaMemsetAsync(ovfcp, 0, sizeof(int));

    // fused GEMM + fill, 1:2 interleaved block types
    int nGemm = (M + BM - 1) / BM;
    int nFill = ((nE + 3) / 4 + 255) / 256;
    gemm_fill_kernel<<<nGemm + nFill, 256>>>(x, weight, support, M, nGemm,
                                             edge_src, edge_dst, edge_val, nE);

    // per-node gather (+bias, +overflow), one store per node
    gather_kernel<<<(M * 32 + 255) / 256, 256>>>(support, bias, out, M);
}